// round 16
// baseline (speedup 1.0000x reference)
#include <cuda_runtime.h>
#include <math.h>

#define N_ATOMS 10000
#define N_EDGES 160000
#define NSPEC   8
#define NSTRUCT 8
#define CH      16
#define NMAX    4
#define NBASIS  8
#define LMAXV   3
#define KTOT    256
#define CUTOFF  5.0f
#define PI_F    3.14159265358979f

// ---------------- device scratch ----------------
__device__ float  g_sh[(size_t)N_EDGES * 16];   // CSR order
__device__ float  g_R [(size_t)N_EDGES * 16];   // CSR order (l,n)
__device__ int    g_send[N_EDGES];              // sender per CSR slot
__device__ int    g_rank[N_EDGES];              // edge -> rank within receiver segment
__device__ float  g_cemb[N_ATOMS * CH];
__device__ float  g_h1[N_ATOMS * CH];
__device__ float4 g_pos4[N_ATOMS];
__device__ float  g_wp[KTOT];                   // w_out[l,n,c] * rsqrt(2l+1)
__device__ int    g_deg[N_ATOMS];               // zero at entry (re-zeroed by k_scan)
__device__ int    g_off[N_ATOMS + 1];

// ---------------- prep: cemb, pos4, w', hist+rank, out zero (one pass) ----------------
__global__ void k_prep(const float* __restrict__ embed, const int* __restrict__ species,
                       const float* __restrict__ pos, const float* __restrict__ w_out,
                       const int* __restrict__ recv, float* __restrict__ out) {
    int i = blockIdx.x * blockDim.x + threadIdx.x;
    if (i < N_EDGES) {
        g_rank[i] = atomicAdd(&g_deg[recv[i]], 1);
        g_cemb[i] = embed[species[i >> 4] * CH + (i & 15)];   // N_ATOMS*CH == N_EDGES
    }
    if (i < N_ATOMS)
        g_pos4[i] = make_float4(pos[3 * i], pos[3 * i + 1], pos[3 * i + 2], 0.f);
    if (i < KTOT) {
        int l = i >> 6;
        g_wp[i] = w_out[i] * rsqrtf(2.0f * (float)l + 1.0f);
    }
    if (i < NSTRUCT) out[i] = 0.f;
}

// ---------------- exclusive scan; writes sentinel; re-zeroes g_deg ----------------
__global__ void __launch_bounds__(1024) k_scan() {
    const int CHUNK = 10;
    int t = threadIdx.x;
    int lane = t & 31, warp = t >> 5;
    int start = t * CHUNK;

    int v[CHUNK];
    int s = 0;
#pragma unroll
    for (int i = 0; i < CHUNK; i++) {
        int idx = start + i;
        v[i] = (idx < N_ATOMS) ? g_deg[idx] : 0;
        s += v[i];
    }
    int x = s;
#pragma unroll
    for (int o = 1; o < 32; o <<= 1) {
        int y = __shfl_up_sync(0xFFFFFFFFu, x, o);
        if (lane >= o) x += y;
    }
    __shared__ int ws[32];
    if (lane == 31) ws[warp] = x;
    __syncthreads();
    if (warp == 0) {
        int wv = ws[lane];
#pragma unroll
        for (int o = 1; o < 32; o <<= 1) {
            int y = __shfl_up_sync(0xFFFFFFFFu, wv, o);
            if (lane >= o) wv += y;
        }
        ws[lane] = wv;
    }
    __syncthreads();
    int run = x - s + ((warp > 0) ? ws[warp - 1] : 0);
#pragma unroll
    for (int i = 0; i < CHUNK; i++) {
        int idx = start + i;
        if (idx < N_ATOMS) { g_off[idx] = run; g_deg[idx] = 0; }
        run += v[i];
    }
    if (t == 0) g_off[N_ATOMS] = N_EDGES;
}

// ---------------- per-edge: sh[16] + R[16] written at CSR slot ----------------
__global__ void k_edges(const int* __restrict__ senders,
                        const int* __restrict__ recv,
                        const float* __restrict__ W_rad) {
    __shared__ float wrad[(LMAXV + 1) * NBASIS * NMAX];
    if (threadIdx.x < (LMAXV + 1) * NBASIS * NMAX) wrad[threadIdx.x] = W_rad[threadIdx.x];
    __syncthreads();

    int e = blockIdx.x * blockDim.x + threadIdx.x;
    if (e >= N_EDGES) return;
    int s = senders[e], r = recv[e];
    int posn = g_off[r] + g_rank[e];
    float4 ps = g_pos4[s];
    float4 pr = g_pos4[r];
    float dx = pr.x - ps.x, dy = pr.y - ps.y, dz = pr.z - ps.z;
    float rn = sqrtf(dx * dx + dy * dy + dz * dz);
    float inv_u = __frcp_rn(fmaxf(rn, 1e-6f));
    float x = dx * inv_u, y = dy * inv_u, z = dz * inv_u;
    float x2 = x * x, y2 = y * y, z2 = z * z;

    float sh[16];
    sh[0]  = 0.28209479f;
    sh[1]  = 0.48860251f * y;
    sh[2]  = 0.48860251f * z;
    sh[3]  = 0.48860251f * x;
    sh[4]  = 1.09254843f * x * y;
    sh[5]  = 1.09254843f * y * z;
    sh[6]  = 0.31539157f * (3.0f * z2 - 1.0f);
    sh[7]  = 1.09254843f * x * z;
    sh[8]  = 0.54627422f * (x2 - y2);
    sh[9]  = 0.59004359f * y * (3.0f * x2 - y2);
    sh[10] = 2.89061144f * x * y * z;
    sh[11] = 0.45704579f * y * (5.0f * z2 - 1.0f);
    sh[12] = 0.37317633f * z * (5.0f * z2 - 3.0f);
    sh[13] = 0.45704579f * x * (5.0f * z2 - 1.0f);
    sh[14] = 1.44530572f * z * (x2 - y2);
    sh[15] = 0.59004359f * x * (x2 - 3.0f * y2);

    float rr = fmaxf(rn, 1e-6f);
    float theta = PI_F * (1.0f / CUTOFF) * rr;
    float s1, c1;
    sincosf(theta, &s1, &c1);
    float fc = (theta < PI_F) ? 0.5f * (c1 + 1.0f) : 0.0f;
    float pref = 0.63245553f * inv_u * fc;
    float bf[NBASIS];
    {
        float sk = s1, ck = c1;
        bf[0] = pref * sk;
#pragma unroll
        for (int n = 1; n < NBASIS; n++) {
            float sn = fmaf(sk, c1, ck * s1);
            float cn = fmaf(ck, c1, -sk * s1);
            sk = sn; ck = cn;
            bf[n] = pref * sk;
        }
    }

    float4 Rq[LMAXV + 1];
#pragma unroll
    for (int l = 0; l <= LMAXV; l++) {
        float a0 = 0.f, a1 = 0.f, a2 = 0.f, a3 = 0.f;
#pragma unroll
        for (int b = 0; b < NBASIS; b++) {
            const float* wl = &wrad[l * (NBASIS * NMAX) + b * NMAX];
            a0 = fmaf(bf[b], wl[0], a0);
            a1 = fmaf(bf[b], wl[1], a1);
            a2 = fmaf(bf[b], wl[2], a2);
            a3 = fmaf(bf[b], wl[3], a3);
        }
        Rq[l] = make_float4(a0, a1, a2, a3);
    }

    g_send[posn] = s;
    float4* SH4 = (float4*)&g_sh[(size_t)posn * 16];
    SH4[0] = make_float4(sh[0],  sh[1],  sh[2],  sh[3]);
    SH4[1] = make_float4(sh[4],  sh[5],  sh[6],  sh[7]);
    SH4[2] = make_float4(sh[8],  sh[9],  sh[10], sh[11]);
    SH4[3] = make_float4(sh[12], sh[13], sh[14], sh[15]);
    float4* R4p = (float4*)&g_R[(size_t)posn * 16];
    R4p[0] = Rq[0]; R4p[1] = Rq[1]; R4p[2] = Rq[2]; R4p[3] = Rq[3];
}

// ---------------- split-channel warps: 2 warps per atom, 8 channels each ----------------
// block = 128 thr = 4 warps = 2 atoms. warp w: atom = 2*blk + (w>>1), cside = w&1.
// lane: jg = lane&15 (j = l(jg)^2 + m), chq = lane>>4 -> channel quad cside*8+chq*4.
// acc[4 n][4 c] in registers; m-reduction via predicated shfl tree.
template<bool FINAL>
__global__ void __launch_bounds__(128, 8) k_layer(
    int use_h1,
    const float* __restrict__ W,       // W_inv1 (non-final)
    const float* __restrict__ comp_w,  // final
    const int* __restrict__ species,   // final
    const int* __restrict__ sid,       // final
    float* __restrict__ out)           // final
{
    const float* __restrict__ h_in = use_h1 ? g_h1 : g_cemb;
    int warp = threadIdx.x >> 5, lane = threadIdx.x & 31;
    int aIdx = warp >> 1, cside = warp & 1;
    int atom = (blockIdx.x << 1) + aIdx;
    int jg = lane & 15, chq = lane >> 4;
    int hoff = (cside << 1) + chq;                 // float4 index within h row
    int l = (jg == 0) ? 0 : (jg < 4) ? 1 : (jg < 9) ? 2 : 3;

    int off = g_off[atom];
    int cnt = g_off[atom + 1] - off;

    float acc[4][4];
#pragma unroll
    for (int n = 0; n < 4; n++)
#pragma unroll
        for (int cc = 0; cc < 4; cc++) acc[n][cc] = 0.f;

    const float* shp = g_sh + (size_t)off * 16 + jg;
    const float* Rp  = g_R  + (size_t)off * 16 + 4 * l;
    const int*   sp  = g_send + off;
    const float4* h4 = (const float4*)h_in;

#define ACCROW(n, u, hv) \
        acc[n][0] = fmaf(u, hv.x, acc[n][0]); acc[n][1] = fmaf(u, hv.y, acc[n][1]); \
        acc[n][2] = fmaf(u, hv.z, acc[n][2]); acc[n][3] = fmaf(u, hv.w, acc[n][3]);

    int s0 = (cnt > 0) ? sp[0] : 0;
    int s1 = (cnt > 1) ? sp[1] : 0;
    int k = 0;
    for (; k + 1 < cnt; k += 2) {
        float  shv0 = shp[(size_t)k * 16];
        float  shv1 = shp[(size_t)(k + 1) * 16];
        float4 R40  = *(const float4*)(Rp + (size_t)k * 16);
        float4 R41  = *(const float4*)(Rp + (size_t)(k + 1) * 16);
        float4 h0   = h4[s0 * 4 + hoff];
        float4 h1   = h4[s1 * 4 + hoff];
        if (k + 2 < cnt) s0 = sp[k + 2];
        if (k + 3 < cnt) s1 = sp[k + 3];

        float u0 = shv0 * R40.x, u1 = shv0 * R40.y, u2 = shv0 * R40.z, u3 = shv0 * R40.w;
        ACCROW(0, u0, h0) ACCROW(1, u1, h0) ACCROW(2, u2, h0) ACCROW(3, u3, h0)
        float v0 = shv1 * R41.x, v1 = shv1 * R41.y, v2 = shv1 * R41.z, v3 = shv1 * R41.w;
        ACCROW(0, v0, h1) ACCROW(1, v1, h1) ACCROW(2, v2, h1) ACCROW(3, v3, h1)
    }
    if (k < cnt) {
        float  shv = shp[(size_t)k * 16];
        float4 R4  = *(const float4*)(Rp + (size_t)k * 16);
        float4 hv  = h4[s0 * 4 + hoff];
        float u0 = shv * R4.x, u1 = shv * R4.y, u2 = shv * R4.z, u3 = shv * R4.w;
        ACCROW(0, u0, hv) ACCROW(1, u1, hv) ACCROW(2, u2, hv) ACCROW(3, u3, hv)
    }
#undef ACCROW

    if (FINAL) {
        // e = sum_{j,c} A^2 * w'[l,n,c] over this warp's channels; all in registers
        const float* wp = g_wp + l * 64 + (cside << 3) + (chq << 2);   // + n*16 + cc
        float part = 0.f;
#pragma unroll
        for (int n = 0; n < 4; n++) {
            const float* wn = wp + n * 16;
#pragma unroll
            for (int cc = 0; cc < 4; cc++) {
                float a = acc[n][cc];
                part = fmaf(a * a, wn[cc], part);
            }
        }
#pragma unroll
        for (int o = 16; o > 0; o >>= 1)
            part += __shfl_down_sync(0xFFFFFFFFu, part, o);
        __shared__ float ev[4];
        if (lane == 0) ev[warp] = part;
        __syncthreads();
        if (threadIdx.x == 0) {
            int a0 = (blockIdx.x << 1), a1 = a0 + 1;
            float e0 = ev[0] + ev[1] + comp_w[species[a0]];
            float e1 = ev[2] + ev[3] + comp_w[species[a1]];
            int i0 = sid[a0], i1 = sid[a1];
            if (i0 == i1) atomicAdd(&out[i0], e0 + e1);
            else { atomicAdd(&out[i0], e0); atomicAdd(&out[i1], e1); }
        }
    } else {
        __shared__ float sminv[2][KTOT];     // per atom
        __shared__ float pcomb[4][16];

        // square in place
#pragma unroll
        for (int n = 0; n < 4; n++)
#pragma unroll
            for (int cc = 0; cc < 4; cc++)
                acc[n][cc] *= acc[n][cc];

        // predicated shfl tree over the m-group (contiguous jg lanes within each half)
        int o = jg - l * l;
        int span = 2 * l;
#pragma unroll
        for (int d = 1; d <= 4; d <<= 1) {
            bool take = (o + d) <= span;
#pragma unroll
            for (int n = 0; n < 4; n++)
#pragma unroll
                for (int cc = 0; cc < 4; cc++) {
                    float t = __shfl_down_sync(0xFFFFFFFFu, acc[n][cc], d);
                    if (take) acc[n][cc] += t;
                }
        }

        // leaders (o==0) publish inv[l, n, this warp's 4 channels]
        float* sv = sminv[aIdx];
        if (o == 0) {
            float sc = rsqrtf(2.0f * (float)l + 1.0f);
            int base = l * 64 + (cside << 3) + (chq << 2);
#pragma unroll
            for (int n = 0; n < 4; n++)
#pragma unroll
                for (int cc = 0; cc < 4; cc++)
                    sv[base + n * 16 + cc] = acc[n][cc] * sc;
        }
        __syncthreads();

        // W-matmul: warp handles its 128-jj block; half picks 64-jj sub-block
        int cp = lane & 15, half = lane >> 4;
        int jbase = (cside << 7) + (half << 6);
        float p0 = 0.f, p1 = 0.f;
#pragma unroll 8
        for (int i = 0; i < 64; i += 2) {
            int jj = jbase + i;
            p0 = fmaf(sv[jj],     W[jj * 16 + cp],       p0);
            p1 = fmaf(sv[jj + 1], W[(jj + 1) * 16 + cp], p1);
        }
        float p = p0 + p1;
        p += __shfl_down_sync(0xFFFFFFFFu, p, 16);
        if (lane < 16) pcomb[warp][lane] = p;
        __syncthreads();
        if (cside == 0 && lane < 16) {
            float tot = pcomb[warp][lane] + pcomb[warp + 1][lane];
            g_h1[atom * CH + lane] = tot * g_cemb[atom * CH + lane];
        }
    }
}

// ---------------- launch ----------------
extern "C" void kernel_launch(void* const* d_in, const int* in_sizes, int n_in,
                              void* d_out, int out_size) {
    const float* positions  = (const float*)d_in[0];
    const float* embed      = (const float*)d_in[1];
    const float* W_rad      = (const float*)d_in[2];
    const float* W_inv1     = (const float*)d_in[3];
    // d_in[4] = W_inv2 is dead: reference returns inv2 before applying it
    const float* w_out      = (const float*)d_in[5];
    const float* comp_w     = (const float*)d_in[6];
    const int*   senders    = (const int*)d_in[7];
    const int*   receivers  = (const int*)d_in[8];
    const int*   species    = (const int*)d_in[9];
    const int*   struct_ids = (const int*)d_in[10];
    float* out = (float*)d_out;

    k_prep<<<(N_EDGES + 255) / 256, 256>>>(embed, species, positions, w_out, receivers, out);
    k_scan<<<1, 1024>>>();
    k_edges<<<(N_EDGES + 255) / 256, 256>>>(senders, receivers, W_rad);

    k_layer<false><<<N_ATOMS / 2, 128>>>(0, W_inv1, nullptr, nullptr, nullptr, nullptr);
    k_layer<true><<<N_ATOMS / 2, 128>>>(1, nullptr, comp_w, species, struct_ids, out);
}